// round 16
// baseline (speedup 1.0000x reference)
#include <cuda_runtime.h>

// Shapes (this instance): B=2048, L=196, M=16, NBL=10. Derived from in_sizes.
#define MAXSITES 256
#define MAXPAIRS 128
#define VSTRIDE 18                      // float2 per chain row (144B)

typedef unsigned long long ull;

// Fused pair tensors (R11-validated):
//  g_QL[p] half0[(m*8+q)] = {P00[m][q],P00[m][q+8],P01[m][q],P01[m][q+8]}
//          half1 = {P10...,P11...};  P_ij = A_i[2p] @ A_j[2p+1]
//  g_QR[p]: right pair p, transposed; P_ij = A_i[Lm2-2-2p] @ A_j[Lm2-1-2p]
__device__ float4 g_QL[MAXPAIRS * 256];
__device__ float4 g_QR[MAXPAIRS * 256];
// Single-site column packs (odd-tail steps):
__device__ float4 g_mat4L[MAXSITES * 128];
__device__ float4 g_mat4R[MAXSITES * 128];

// ---------------------------------------------------------------------------
__device__ __forceinline__ ull pack2(float x, float y) {
    ull r; asm("mov.b64 %0, {%1,%2};" : "=l"(r) : "f"(x), "f"(y)); return r;
}
__device__ __forceinline__ void unpack2(ull v, float& x, float& y) {
    asm("mov.b64 {%0,%1}, %2;" : "=f"(x), "=f"(y) : "l"(v));
}
__device__ __forceinline__ void fma2(ull& d, ull a, ull b) {
    asm("fma.rn.f32x2 %0, %1, %2, %0;" : "+l"(d) : "l"(a), "l"(b));
}
__device__ __forceinline__ ull mul2(ull a, ull b) {
    ull d; asm("mul.rn.f32x2 %0, %1, %2;" : "=l"(d) : "l"(a), "l"(b)); return d;
}

// ---------------------------------------------------------------------------
// Kernel 1: prep (unchanged from R14). One site-pair job per block, 256 thr.
// ---------------------------------------------------------------------------
__global__ void __launch_bounds__(256)
prep_kernel(const float* __restrict__ A_mid, int Lm2) {
    __shared__ __align__(16) float sF[512];
    __shared__ __align__(16) float sS[512];
    int t = threadIdx.x;
    int PL = Lm2 >> 1;
    bool right = (blockIdx.x >= (unsigned)PL);
    int p = right ? blockIdx.x - PL : blockIdx.x;
    int sFirst  = right ? (Lm2 - 2 - 2 * p) : (2 * p);
    int sSecond = right ? (Lm2 - 1 - 2 * p) : (2 * p + 1);

    if (t < 128)
        ((float4*)sF)[t] = __ldg((const float4*)(A_mid + sFirst * 512) + t);
    else
        ((float4*)sS)[t - 128] = __ldg((const float4*)(A_mid + sSecond * 512) + (t - 128));
    __syncthreads();

    if (!right) {
        int site = 2 * p + (t >> 7);
        const float* S = (t < 128) ? sF : sS;
        int e = t & 127;
        int m = e >> 3, qq = e & 7;
        g_mat4L[site * 128 + e] =
            make_float4(S[m * 16 + qq], S[m * 16 + qq + 8],
                        S[256 + m * 16 + qq], S[256 + m * 16 + qq + 8]);
        g_mat4R[(Lm2 - 1 - site) * 128 + e] =
            make_float4(S[qq * 16 + m], S[(qq + 8) * 16 + m],
                        S[256 + qq * 16 + m], S[256 + (qq + 8) * 16 + m]);
        if (p == 0 && (Lm2 & 1) && t < 128) {
            int s2 = Lm2 - 1;
            const float* A0 = A_mid + s2 * 512;
            const float* A1 = A0 + 256;
            g_mat4L[s2 * 128 + t] =
                make_float4(A0[m * 16 + qq], A0[m * 16 + qq + 8],
                            A1[m * 16 + qq], A1[m * 16 + qq + 8]);
            g_mat4R[(Lm2 - 1 - s2) * 128 + t] =
                make_float4(A0[qq * 16 + m], A0[(qq + 8) * 16 + m],
                            A1[qq * 16 + m], A1[(qq + 8) * 16 + m]);
        }
    }

    int h   = t >> 7;
    int idx = t & 127;
    int m = idx >> 3, qq = idx & 7;
    int rA0 = right ? qq       : m;
    int rA1 = right ? (qq + 8) : m;
    int cB0 = right ? m        : qq;
    int cB1 = right ? m        : (qq + 8);
    const float* F = sF + h * 256;
    float o0 = 0.f, o1 = 0.f, o2 = 0.f, o3 = 0.f;
#pragma unroll
    for (int k = 0; k < 16; ++k) {
        float fa = F[rA0 * 16 + k], fb = F[rA1 * 16 + k];
        float s0a = sS[k * 16 + cB0],       s0b = sS[k * 16 + cB1];
        float s1a = sS[256 + k * 16 + cB0], s1b = sS[256 + k * 16 + cB1];
        o0 = fmaf(fa, s0a, o0);  o1 = fmaf(fb, s0b, o1);
        o2 = fmaf(fa, s1a, o2);  o3 = fmaf(fb, s1b, o3);
    }
    float4* dst = (right ? g_QR : g_QL) + p * 256;
    dst[h * 128 + idx] = make_float4(o0, o1, o2, o3);
}

// ---------------------------------------------------------------------------
// Kernel 2: chains + fused combine. C=8 chains/warp (R14 winner geometry),
// but matrix operands read DIRECTLY from global via __ldg (L1-cached,
// shared across same-direction warps on the SM) — no cp.async ring, no
// staging traffic. v exchanged via smem splats, one __syncwarp per step.
// Block = 64 thr = 8 samples. Warp 0: LEFT, warp 1: RIGHT.
// Lane: q = lane&7 owns components {q,q+8} of samples ch and ch+4.
// ---------------------------------------------------------------------------
__global__ void __launch_bounds__(64)
chain_kernel(const float* __restrict__ inputs,
             const float* __restrict__ A_left,
             const float* __restrict__ A_right,
             const float* __restrict__ T,
             const int*   __restrict__ pos_ptr,
             float* __restrict__ out,
             int B, int L, int NBL) {
    __shared__ __align__(16) float2 sVs[2 * 16 * VSTRIDE];  // v splats
    __shared__ __align__(16) float  sLR[256];               // results
    __shared__ __align__(16) float  sT[2816];               // T cache (>=256*NBL, NBL<=11)

    int tid  = threadIdx.x;
    int w    = tid >> 5;                                 // 0 = left, 1 = right
    int lane = tid & 31;
    int q    = lane & 7;
    int ch   = lane >> 3;                                // 0..3

    const int Lm2 = L - 2;
    const float2* in2 = (const float2*)inputs;           // (B,L) float2

    int pos = __ldg(pos_ptr);
    bool isLeft = (w == 0);
    int sm0 = ch, sm1 = ch + 4;
    int cidx0 = w * 8 + sm0;
    int cidx1 = w * 8 + sm1;
    int c0 = blockIdx.x * 8 + sm0;
    int c1 = blockIdx.x * 8 + sm1;
    int nsites = isLeft ? pos : (Lm2 - pos);
    int P = nsites >> 1;
    const float* seedA = isLeft ? A_left : A_right;
    int seedX = isLeft ? 0 : (L - 1);

    float sa0 = __ldg(seedA + q),     sa1 = __ldg(seedA + 16 + q);
    float sb0 = __ldg(seedA + q + 8), sb1 = __ldg(seedA + 16 + q + 8);
    float2 xsA = __ldg(in2 + c0 * L + seedX);
    float2 xsB = __ldg(in2 + c1 * L + seedX);
    float vA0 = fmaf(xsA.y, sa1, xsA.x * sa0);
    float vA1 = fmaf(xsA.y, sb1, xsA.x * sb0);
    float vB0 = fmaf(xsB.y, sa1, xsB.x * sa0);
    float vB1 = fmaf(xsB.y, sb1, xsB.x * sb0);
    {   // seed splats -> buffer 0
        float2* dA = sVs + cidx0 * VSTRIDE;
        float2* dB = sVs + cidx1 * VSTRIDE;
        dA[q] = make_float2(vA0, vA0); dA[q + 8] = make_float2(vA1, vA1);
        dB[q] = make_float2(vB0, vB0); dB[q + 8] = make_float2(vB1, vB1);
    }

    // matrix tile base for this lane (gmem, L1-resident across warps)
    const ulonglong2* QTq = (const ulonglong2*)(isLeft ? g_QL : g_QR) + q;

    auto make_coef = [&](float2 xi, float2 xj, ull* c) {
        c[0] = pack2(xi.x * xj.x, xi.x * xj.x);
        c[1] = pack2(xi.x * xj.y, xi.x * xj.y);
        c[2] = pack2(xi.y * xj.x, xi.y * xj.x);
        c[3] = pack2(xi.y * xj.y, xi.y * xj.y);
    };

    auto do_step = [&](int t, const ull* cA, const ull* cB) {
        const ulonglong2* tl = QTq + t * 256;     // half0 rows; half1 at +128
        int vb = t & 1;
        ull vA[16], vB[16];
        {
            const ulonglong2* pa =
                (const ulonglong2*)(sVs + vb * 16 * VSTRIDE + cidx0 * VSTRIDE);
            const ulonglong2* pb =
                (const ulonglong2*)(sVs + vb * 16 * VSTRIDE + cidx1 * VSTRIDE);
#pragma unroll
            for (int j = 0; j < 8; ++j) {
                ulonglong2 ta = pa[j]; vA[2 * j] = ta.x; vA[2 * j + 1] = ta.y;
                ulonglong2 tb = pb[j]; vB[2 * j] = tb.x; vB[2 * j + 1] = tb.y;
            }
        }
        ull aA0=0ull,aA1=0ull,aA2=0ull,aA3=0ull;
        ull aB0=0ull,aB1=0ull,aB2=0ull,aB3=0ull;
#pragma unroll
        for (int m = 0; m < 16; ++m) {
            ulonglong2 M0 = __ldg(tl + m * 8);
            ulonglong2 M1 = __ldg(tl + 128 + m * 8);
            fma2(aA0, vA[m], M0.x); fma2(aA1, vA[m], M0.y);
            fma2(aA2, vA[m], M1.x); fma2(aA3, vA[m], M1.y);
            fma2(aB0, vB[m], M0.x); fma2(aB1, vB[m], M0.y);
            fma2(aB2, vB[m], M1.x); fma2(aB3, vB[m], M1.y);
        }
        ull rA0 = mul2(cA[0], aA0); fma2(rA0, cA[1], aA1);
        ull rA1 = mul2(cA[2], aA2); fma2(rA1, cA[3], aA3);
        ull rA; asm("add.rn.f32x2 %0, %1, %2;" : "=l"(rA) : "l"(rA0), "l"(rA1));
        unpack2(rA, vA0, vA1);
        ull rB0 = mul2(cB[0], aB0); fma2(rB0, cB[1], aB1);
        ull rB1 = mul2(cB[2], aB2); fma2(rB1, cB[3], aB3);
        ull rB; asm("add.rn.f32x2 %0, %1, %2;" : "=l"(rB) : "l"(rB0), "l"(rB1));
        unpack2(rB, vB0, vB1);

        float2* dA = sVs + (1 - vb) * 16 * VSTRIDE + cidx0 * VSTRIDE;
        float2* dB = sVs + (1 - vb) * 16 * VSTRIDE + cidx1 * VSTRIDE;
        dA[q] = make_float2(vA0, vA0); dA[q + 8] = make_float2(vA1, vA1);
        dB[q] = make_float2(vB0, vB0); dB[q + 8] = make_float2(vB1, vB1);
    };

    // ---- warp-autonomous main loop: no staging, no block barriers -----------
    ull cA[4], cB[4];
    if (P > 0) {
        int siteI = isLeft ? 1 : (L - 3);
        int siteJ = isLeft ? 2 : (L - 2);
        make_coef(__ldg(in2 + c0 * L + siteI), __ldg(in2 + c0 * L + siteJ), cA);
        make_coef(__ldg(in2 + c1 * L + siteI), __ldg(in2 + c1 * L + siteJ), cB);
    }
    for (int t = 0; t < P; ++t) {
        float2 nxiA, nxjA, nxiB, nxjB;
        bool more = (t + 1 < P);
        if (more) {                        // rolling x prefetch
            int siteI = isLeft ? (3 + 2 * t) : (L - 5 - 2 * t);
            int siteJ = isLeft ? (4 + 2 * t) : (L - 4 - 2 * t);
            nxiA = __ldg(in2 + c0 * L + siteI); nxjA = __ldg(in2 + c0 * L + siteJ);
            nxiB = __ldg(in2 + c1 * L + siteI); nxjB = __ldg(in2 + c1 * L + siteJ);
        }
        __syncwarp();                      // publish prev-step v STS
        do_step(t, cA, cB);
        if (more) {
            make_coef(nxiA, nxjA, cA);
            make_coef(nxiB, nxjB, cB);
        }
    }
    __syncwarp();                          // order last v STS before tail read

    // ---- odd tail: one single-site step --------------------------------------
    if (nsites & 1) {
        int vb = P & 1;
        ull vA[16], vB[16];
        {
            const ulonglong2* pa =
                (const ulonglong2*)(sVs + vb * 16 * VSTRIDE + cidx0 * VSTRIDE);
            const ulonglong2* pb =
                (const ulonglong2*)(sVs + vb * 16 * VSTRIDE + cidx1 * VSTRIDE);
#pragma unroll
            for (int j = 0; j < 8; ++j) {
                ulonglong2 ta = pa[j]; vA[2 * j] = ta.x; vA[2 * j + 1] = ta.y;
                ulonglong2 tb = pb[j]; vB[2 * j] = tb.x; vB[2 * j + 1] = tb.y;
            }
        }
        int s = 2 * P;
        const float4* mat = (isLeft ? g_mat4L : g_mat4R) + s * 128;
        int xin = isLeft ? (1 + s) : (L - 2 - s);
        float2 xA = __ldg(in2 + c0 * L + xin);
        float2 xB = __ldg(in2 + c1 * L + xin);
        ull a0A=0ull,a1A=0ull,a0B=0ull,a1B=0ull;
#pragma unroll
        for (int m = 0; m < 16; ++m) {
            float4 Mf = __ldg(mat + m * 8 + q);
            ull M0 = pack2(Mf.x, Mf.y), M1 = pack2(Mf.z, Mf.w);
            fma2(a0A, vA[m], M0); fma2(a1A, vA[m], M1);
            fma2(a0B, vB[m], M0); fma2(a1B, vB[m], M1);
        }
        ull rA = mul2(pack2(xA.x, xA.x), a0A);
        fma2(rA, pack2(xA.y, xA.y), a1A);
        unpack2(rA, vA0, vA1);
        ull rB = mul2(pack2(xB.x, xB.x), a0B);
        fma2(rB, pack2(xB.y, xB.y), a1B);
        unpack2(rB, vB0, vB1);
    }

    // ---- publish chain results, fused combine ---------------------------------
    float* sL = sLR;
    float* sR = sLR + 128;
    {
        float* d = (isLeft ? sL : sR);
        d[sm0 * 16 + q] = vA0; d[sm0 * 16 + q + 8] = vA1;
        d[sm1 * 16 + q] = vB0; d[sm1 * 16 + q + 8] = vB1;
    }
    __syncthreads();

    int tElems = 256 * NBL;
    for (int i = tid; i < tElems; i += 64) sT[i] = __ldg(T + i);
    __syncthreads();

    int total = 8 * NBL;
    for (int i = tid; i < total; i += 64) {
        int b = i / NBL, l = i - b * NBL;
        float acc = 0.f;
#pragma unroll
        for (int m = 0; m < 16; ++m) {
            float t2 = 0.f;
#pragma unroll
            for (int k = 0; k < 16; ++k)
                t2 = fmaf(sT[(m * 16 + k) * NBL + l], sR[b * 16 + k], t2);
            acc = fmaf(sL[b * 16 + m], t2, acc);
        }
        out[(blockIdx.x * 8 + b) * NBL + l] = acc;
    }
}

// ---------------------------------------------------------------------------
extern "C" void kernel_launch(void* const* d_in, const int* in_sizes, int n_in,
                              void* d_out, int out_size) {
    const float* inputs  = (const float*)d_in[0];
    const float* A_left  = (const float*)d_in[1];
    const float* A_mid   = (const float*)d_in[2];
    const float* A_right = (const float*)d_in[3];
    const float* T_out   = (const float*)d_in[4];
    const int*   pos     = (const int*)d_in[5];

    int Lm2 = in_sizes[2] / 512;          // L-2 = 194
    int L   = Lm2 + 2;                    // 196
    int B   = in_sizes[0] / (2 * L);      // 2048
    int NBL = in_sizes[4] / 256;          // 10

    int PL = Lm2 >> 1;                    // 97
    prep_kernel<<<2 * PL, 256>>>(A_mid, Lm2);

    int nblocks = B / 8;                  // 256 blocks, 512 warps
    chain_kernel<<<nblocks, 64>>>(inputs, A_left, A_right,
                                  T_out, pos, (float*)d_out,
                                  B, L, NBL);
}

// round 17
// speedup vs baseline: 1.9108x; 1.9108x over previous
#include <cuda_runtime.h>

// Shapes (this instance): B=2048, L=196, M=16, NBL=10. Derived from in_sizes.
#define MAXSITES 256
#define MAXPAIRS 128
#define MAXQUADS 64
#define QTILE_B 16384                   // quad tile: 1024 float4 (16 matrices)
#define NSLOT   3
#define WRING_B (NSLOT * QTILE_B)       // 48 KB per-warp ring
#define RING_B  (2 * WRING_B)           // 96 KB (2 warps per block)
#define VSTRIDE 18                      // float2 per chain row (144B)
#define SV_B    (2 * 16 * VSTRIDE * 8)  // 4608 B
#define SLR_B   1024

typedef unsigned long long ull;

// Pair tensors (R11-validated) + single-site packs (tails):
__device__ float4 g_QL[MAXPAIRS * 256];
__device__ float4 g_QR[MAXPAIRS * 256];
__device__ float4 g_mat4L[MAXSITES * 128];
__device__ float4 g_mat4R[MAXSITES * 128];
// Quad tensors: g_quad*[p] = 16 matrices P_{(ab),(cd)} = Pair[2p]_{ab} @ Pair[2p+1]_{cd}
// layout: float4[h*128 + m*8 + q] = {G_{2h}[m][q], G_{2h}[m][q+8], G_{2h+1}[m][q], G_{2h+1}[m][q+8]}
__device__ float4 g_quadL[MAXQUADS * 1024];
__device__ float4 g_quadR[MAXQUADS * 1024];

// ---------------------------------------------------------------------------
__device__ __forceinline__ ull pack2(float x, float y) {
    ull r; asm("mov.b64 %0, {%1,%2};" : "=l"(r) : "f"(x), "f"(y)); return r;
}
__device__ __forceinline__ void unpack2(ull v, float& x, float& y) {
    asm("mov.b64 {%0,%1}, %2;" : "=f"(x), "=f"(y) : "l"(v));
}
__device__ __forceinline__ void fma2(ull& d, ull a, ull b) {
    asm("fma.rn.f32x2 %0, %1, %2, %0;" : "+l"(d) : "l"(a), "l"(b));
}
__device__ __forceinline__ ull mul2(ull a, ull b) {
    ull d; asm("mul.rn.f32x2 %0, %1, %2;" : "=l"(d) : "l"(a), "l"(b)); return d;
}
__device__ __forceinline__ void cpasyncCA(unsigned dst, const void* src) {
    asm volatile("cp.async.ca.shared.global [%0], [%1], 16;\n"
                 :: "r"(dst), "l"(src) : "memory");
}
__device__ __forceinline__ void cpcommit() {
    asm volatile("cp.async.commit_group;\n" ::: "memory");
}
template<int N> __device__ __forceinline__ void cpwait() {
    asm volatile("cp.async.wait_group %0;\n" :: "n"(N) : "memory");
}

// ---------------------------------------------------------------------------
// Kernel 1: pair prep (unchanged from R14).
// ---------------------------------------------------------------------------
__global__ void __launch_bounds__(256)
prep_kernel(const float* __restrict__ A_mid, int Lm2) {
    __shared__ __align__(16) float sF[512];
    __shared__ __align__(16) float sS[512];
    int t = threadIdx.x;
    int PL = Lm2 >> 1;
    bool right = (blockIdx.x >= (unsigned)PL);
    int p = right ? blockIdx.x - PL : blockIdx.x;
    int sFirst  = right ? (Lm2 - 2 - 2 * p) : (2 * p);
    int sSecond = right ? (Lm2 - 1 - 2 * p) : (2 * p + 1);

    if (t < 128)
        ((float4*)sF)[t] = __ldg((const float4*)(A_mid + sFirst * 512) + t);
    else
        ((float4*)sS)[t - 128] = __ldg((const float4*)(A_mid + sSecond * 512) + (t - 128));
    __syncthreads();

    if (!right) {
        int site = 2 * p + (t >> 7);
        const float* S = (t < 128) ? sF : sS;
        int e = t & 127;
        int m = e >> 3, qq = e & 7;
        g_mat4L[site * 128 + e] =
            make_float4(S[m * 16 + qq], S[m * 16 + qq + 8],
                        S[256 + m * 16 + qq], S[256 + m * 16 + qq + 8]);
        g_mat4R[(Lm2 - 1 - site) * 128 + e] =
            make_float4(S[qq * 16 + m], S[(qq + 8) * 16 + m],
                        S[256 + qq * 16 + m], S[256 + (qq + 8) * 16 + m]);
        if (p == 0 && (Lm2 & 1) && t < 128) {
            int s2 = Lm2 - 1;
            const float* A0 = A_mid + s2 * 512;
            const float* A1 = A0 + 256;
            g_mat4L[s2 * 128 + t] =
                make_float4(A0[m * 16 + qq], A0[m * 16 + qq + 8],
                            A1[m * 16 + qq], A1[m * 16 + qq + 8]);
            g_mat4R[(Lm2 - 1 - s2) * 128 + t] =
                make_float4(A0[qq * 16 + m], A0[(qq + 8) * 16 + m],
                            A1[qq * 16 + m], A1[(qq + 8) * 16 + m]);
        }
    }

    int h   = t >> 7;
    int idx = t & 127;
    int m = idx >> 3, qq = idx & 7;
    int rA0 = right ? qq       : m;
    int rA1 = right ? (qq + 8) : m;
    int cB0 = right ? m        : qq;
    int cB1 = right ? m        : (qq + 8);
    const float* F = sF + h * 256;
    float o0 = 0.f, o1 = 0.f, o2 = 0.f, o3 = 0.f;
#pragma unroll
    for (int k = 0; k < 16; ++k) {
        float fa = F[rA0 * 16 + k], fb = F[rA1 * 16 + k];
        float s0a = sS[k * 16 + cB0],       s0b = sS[k * 16 + cB1];
        float s1a = sS[256 + k * 16 + cB0], s1b = sS[256 + k * 16 + cB1];
        o0 = fmaf(fa, s0a, o0);  o1 = fmaf(fb, s0b, o1);
        o2 = fmaf(fa, s1a, o2);  o3 = fmaf(fb, s1b, o3);
    }
    float4* dst = (right ? g_QR : g_QL) + p * 256;
    dst[h * 128 + idx] = make_float4(o0, o1, o2, o3);
}

// ---------------------------------------------------------------------------
// Kernel 2: quad prep. quad[p] = Pair[2p] @ Pair[2p+1], composed in stored
// form (identical math for both directions; right tiles are pre-transposed).
// One quad per block, 256 threads; thread (g,m) computes row m of G_g.
// ---------------------------------------------------------------------------
__global__ void __launch_bounds__(256)
prep2_kernel(int Lm2) {
    __shared__ float sM1[4][16][16];
    __shared__ float sM2[4][16][16];
    __shared__ float sG[16][16][16];
    int t = threadIdx.x;
    int PL = Lm2 >> 1;
    int QMAX = PL >> 1;
    bool right = blockIdx.x >= (unsigned)QMAX;
    int p = right ? blockIdx.x - QMAX : blockIdx.x;
    const float4* Q1 = (right ? g_QR : g_QL) + (2 * p) * 256;
    const float4* Q2 = (right ? g_QR : g_QL) + (2 * p + 1) * 256;
    {
        int hp = t >> 7;
        int e = t & 127, m = e >> 3, qq = e & 7;
        float4 a = __ldg(Q1 + t);
        sM1[2 * hp][m][qq]     = a.x;  sM1[2 * hp][m][qq + 8]     = a.y;
        sM1[2 * hp + 1][m][qq] = a.z;  sM1[2 * hp + 1][m][qq + 8] = a.w;
        float4 b = __ldg(Q2 + t);
        sM2[2 * hp][m][qq]     = b.x;  sM2[2 * hp][m][qq + 8]     = b.y;
        sM2[2 * hp + 1][m][qq] = b.z;  sM2[2 * hp + 1][m][qq + 8] = b.w;
    }
    __syncthreads();
    {
        int g = t >> 4, m = t & 15;
        int ab = g >> 2, cd = g & 3;
        float outr[16];
#pragma unroll
        for (int n = 0; n < 16; ++n) outr[n] = 0.f;
#pragma unroll
        for (int k = 0; k < 16; ++k) {
            float a = sM1[ab][m][k];
#pragma unroll
            for (int n = 0; n < 16; ++n)
                outr[n] = fmaf(a, sM2[cd][k][n], outr[n]);
        }
#pragma unroll
        for (int n = 0; n < 16; ++n) sG[g][m][n] = outr[n];
    }
    __syncthreads();
    {
        float4* dst = (right ? g_quadR : g_quadL) + p * 1024;
        for (int i = t; i < 1024; i += 256) {
            int h = i >> 7, e = i & 127, m = e >> 3, qq = e & 7;
            dst[i] = make_float4(sG[2 * h][m][qq],     sG[2 * h][m][qq + 8],
                                 sG[2 * h + 1][m][qq], sG[2 * h + 1][m][qq + 8]);
        }
    }
}

// ---------------------------------------------------------------------------
// Kernel 3: chains + fused combine. R14 geometry (C=8 chains/warp, per-warp
// cp.async ring, smem v splats), but QUAD steps: 4 sites per step, 24 steps.
// Tails: one pair step (global-direct) if nsites%4>=2, one single if odd.
// ---------------------------------------------------------------------------
__global__ void __launch_bounds__(64, 2)
chain_kernel(const float* __restrict__ inputs,
             const float* __restrict__ A_left,
             const float* __restrict__ A_right,
             const float* __restrict__ T,
             const int*   __restrict__ pos_ptr,
             float* __restrict__ out,
             int B, int L, int NBL) {
    extern __shared__ __align__(16) char smem[];
    const int Lm2 = L - 2;
    char*   ring = smem;                                 // RING_B
    float2* sVs  = (float2*)(smem + RING_B);             // SV_B
    float*  sLR  = (float*)(smem + RING_B + SV_B);       // SLR_B

    int tid  = threadIdx.x;
    int w    = tid >> 5;
    int lane = tid & 31;
    int q    = lane & 7;
    int ch   = lane >> 3;

    const float2* in2 = (const float2*)inputs;

    int pos = __ldg(pos_ptr);
    bool isLeft = (w == 0);
    int sm0 = ch, sm1 = ch + 4;
    int cidx0 = w * 8 + sm0;
    int cidx1 = w * 8 + sm1;
    int c0 = blockIdx.x * 8 + sm0;
    int c1 = blockIdx.x * 8 + sm1;
    int nsites = isLeft ? pos : (Lm2 - pos);
    int Q = nsites >> 2;
    int r = nsites & 3;
    const float* seedA = isLeft ? A_left : A_right;
    int seedX = isLeft ? 0 : (L - 1);

    float sa0 = __ldg(seedA + q),     sa1 = __ldg(seedA + 16 + q);
    float sb0 = __ldg(seedA + q + 8), sb1 = __ldg(seedA + 16 + q + 8);
    float2 xsA = __ldg(in2 + c0 * L + seedX);
    float2 xsB = __ldg(in2 + c1 * L + seedX);
    float vA0 = fmaf(xsA.y, sa1, xsA.x * sa0);
    float vA1 = fmaf(xsA.y, sb1, xsA.x * sb0);
    float vB0 = fmaf(xsB.y, sa1, xsB.x * sa0);
    float vB1 = fmaf(xsB.y, sb1, xsB.x * sb0);
    {
        float2* dA = sVs + cidx0 * VSTRIDE;
        float2* dB = sVs + cidx1 * VSTRIDE;
        dA[q] = make_float2(vA0, vA0); dA[q + 8] = make_float2(vA1, vA1);
        dB[q] = make_float2(vB0, vB0); dB[q + 8] = make_float2(vB1, vB1);
    }

    const float4* QT = isLeft ? g_quadL : g_quadR;
    unsigned ringW = (unsigned)__cvta_generic_to_shared(ring) + w * WRING_B;

    auto stage = [&](int p, int slot) {
        if (p < Q) {
            const float4* src = QT + p * 1024;
            unsigned dst = ringW + slot * QTILE_B;
#pragma unroll
            for (int kk = 0; kk < 32; ++kk) {
                int chunk = lane + kk * 32;              // 0..1023
                cpasyncCA(dst + chunk * 16, src + chunk);
            }
        }
        cpcommit();
    };

    // 16 quad coefficients per chain: c[g] = t[ab]*u[cd]
    auto make_coef4 = [&](float2 x1, float2 x2, float2 x3, float2 x4, float* c) {
        float t0 = x1.x * x2.x, t1 = x1.x * x2.y, t2 = x1.y * x2.x, t3 = x1.y * x2.y;
        float u0 = x3.x * x4.x, u1 = x3.x * x4.y, u2 = x3.y * x4.x, u3 = x3.y * x4.y;
        c[0]  = t0 * u0; c[1]  = t0 * u1; c[2]  = t0 * u2; c[3]  = t0 * u3;
        c[4]  = t1 * u0; c[5]  = t1 * u1; c[6]  = t1 * u2; c[7]  = t1 * u3;
        c[8]  = t2 * u0; c[9]  = t2 * u1; c[10] = t2 * u2; c[11] = t2 * u3;
        c[12] = t3 * u0; c[13] = t3 * u1; c[14] = t3 * u2; c[15] = t3 * u3;
    };

    auto load_v = [&](int vb, ull* vA, ull* vB) {
        const ulonglong2* pa =
            (const ulonglong2*)(sVs + vb * 16 * VSTRIDE + cidx0 * VSTRIDE);
        const ulonglong2* pb =
            (const ulonglong2*)(sVs + vb * 16 * VSTRIDE + cidx1 * VSTRIDE);
#pragma unroll
        for (int j = 0; j < 8; ++j) {
            ulonglong2 ta = pa[j]; vA[2 * j] = ta.x; vA[2 * j + 1] = ta.y;
            ulonglong2 tb = pb[j]; vB[2 * j] = tb.x; vB[2 * j + 1] = tb.y;
        }
    };
    auto store_v = [&](int vb) {
        float2* dA = sVs + vb * 16 * VSTRIDE + cidx0 * VSTRIDE;
        float2* dB = sVs + vb * 16 * VSTRIDE + cidx1 * VSTRIDE;
        dA[q] = make_float2(vA0, vA0); dA[q + 8] = make_float2(vA1, vA1);
        dB[q] = make_float2(vB0, vB0); dB[q + 8] = make_float2(vB1, vB1);
    };

    auto do_quad = [&](int t, int slot, const float* cA, const float* cB) {
        const char* tile = ring + w * WRING_B + slot * QTILE_B;
        int vb = t & 1;
        ull vA[16], vB[16];
        load_v(vb, vA, vB);
        ull rA = 0ull, rB = 0ull;
#pragma unroll
        for (int h = 0; h < 8; ++h) {
            const ulonglong2* tl = (const ulonglong2*)(tile + h * 2048) + q;
            ull eA = 0ull, oA = 0ull, eB = 0ull, oB = 0ull;
#pragma unroll
            for (int m = 0; m < 16; ++m) {
                ulonglong2 M = tl[m * 8];
                fma2(eA, vA[m], M.x); fma2(oA, vA[m], M.y);
                fma2(eB, vB[m], M.x); fma2(oB, vB[m], M.y);
            }
            fma2(rA, pack2(cA[2 * h],     cA[2 * h]),     eA);
            fma2(rA, pack2(cA[2 * h + 1], cA[2 * h + 1]), oA);
            fma2(rB, pack2(cB[2 * h],     cB[2 * h]),     eB);
            fma2(rB, pack2(cB[2 * h + 1], cB[2 * h + 1]), oB);
        }
        unpack2(rA, vA0, vA1);
        unpack2(rB, vB0, vB1);
        store_v(1 - vb);
    };

    // ---- main quad loop: 3-slot ring, ~2 steps of slack ----------------------
    stage(0, 0); stage(1, 1);
    float cA[16], cB[16];
    int slotCur = 0, slotPre = 2;
    for (int t = 0; t < Q; ++t) {
        {   // coefficients for step t (loads issue early, used late in step)
            int s1, s2, s3, s4;
            if (isLeft) { s1 = 1 + 4 * t; s2 = s1 + 1; s3 = s1 + 2; s4 = s1 + 3; }
            else { s1 = L - 3 - 4 * t; s2 = L - 2 - 4 * t;
                   s3 = L - 5 - 4 * t; s4 = L - 4 - 4 * t; }
            make_coef4(__ldg(in2 + c0 * L + s1), __ldg(in2 + c0 * L + s2),
                       __ldg(in2 + c0 * L + s3), __ldg(in2 + c0 * L + s4), cA);
            make_coef4(__ldg(in2 + c1 * L + s1), __ldg(in2 + c1 * L + s2),
                       __ldg(in2 + c1 * L + s3), __ldg(in2 + c1 * L + s4), cB);
        }
        cpwait<1>();
        __syncwarp();                      // publish cp.async data + prev v STS
        stage(t + 2, slotPre);
        do_quad(t, slotCur, cA, cB);
        slotCur = (slotCur == NSLOT - 1) ? 0 : slotCur + 1;
        slotPre = (slotPre == NSLOT - 1) ? 0 : slotPre + 1;
    }
    cpwait<0>();
    __syncwarp();                          // order last v STS

    int cur = Q & 1;                       // buffer holding latest v

    // ---- pair tail (nsites%4 >= 2): one pair step, tile direct from global ---
    if (r >= 2) {
        int t2 = 2 * Q;                    // pair index
        ull vA[16], vB[16];
        load_v(cur, vA, vB);
        int siteI = isLeft ? (1 + 2 * t2) : (L - 3 - 2 * t2);
        int siteJ = isLeft ? (2 + 2 * t2) : (L - 2 - 2 * t2);
        float2 xiA = __ldg(in2 + c0 * L + siteI), xjA = __ldg(in2 + c0 * L + siteJ);
        float2 xiB = __ldg(in2 + c1 * L + siteI), xjB = __ldg(in2 + c1 * L + siteJ);
        const ulonglong2* tl = (const ulonglong2*)((isLeft ? g_QL : g_QR) + t2 * 256) + q;
        ull aA0=0ull,aA1=0ull,aA2=0ull,aA3=0ull;
        ull aB0=0ull,aB1=0ull,aB2=0ull,aB3=0ull;
#pragma unroll
        for (int m = 0; m < 16; ++m) {
            ulonglong2 M0 = __ldg(tl + m * 8);
            ulonglong2 M1 = __ldg(tl + 128 + m * 8);
            fma2(aA0, vA[m], M0.x); fma2(aA1, vA[m], M0.y);
            fma2(aA2, vA[m], M1.x); fma2(aA3, vA[m], M1.y);
            fma2(aB0, vB[m], M0.x); fma2(aB1, vB[m], M0.y);
            fma2(aB2, vB[m], M1.x); fma2(aB3, vB[m], M1.y);
        }
        ull rA = mul2(pack2(xiA.x * xjA.x, xiA.x * xjA.x), aA0);
        fma2(rA, pack2(xiA.x * xjA.y, xiA.x * xjA.y), aA1);
        fma2(rA, pack2(xiA.y * xjA.x, xiA.y * xjA.x), aA2);
        fma2(rA, pack2(xiA.y * xjA.y, xiA.y * xjA.y), aA3);
        unpack2(rA, vA0, vA1);
        ull rB = mul2(pack2(xiB.x * xjB.x, xiB.x * xjB.x), aB0);
        fma2(rB, pack2(xiB.x * xjB.y, xiB.x * xjB.y), aB1);
        fma2(rB, pack2(xiB.y * xjB.x, xiB.y * xjB.x), aB2);
        fma2(rB, pack2(xiB.y * xjB.y, xiB.y * xjB.y), aB3);
        unpack2(rB, vB0, vB1);
        store_v(1 - cur);
        __syncwarp();
        cur = 1 - cur;
    }

    // ---- single tail (nsites odd) ---------------------------------------------
    if (r & 1) {
        int d = 4 * Q + ((r >= 2) ? 2 : 0);   // sites already applied
        ull vA[16], vB[16];
        load_v(cur, vA, vB);
        const float4* mat = (isLeft ? g_mat4L : g_mat4R) + d * 128;
        int xin = isLeft ? (1 + d) : (L - 2 - d);
        float2 xA = __ldg(in2 + c0 * L + xin);
        float2 xB = __ldg(in2 + c1 * L + xin);
        ull a0A=0ull,a1A=0ull,a0B=0ull,a1B=0ull;
#pragma unroll
        for (int m = 0; m < 16; ++m) {
            float4 Mf = __ldg(mat + m * 8 + q);
            ull M0 = pack2(Mf.x, Mf.y), M1 = pack2(Mf.z, Mf.w);
            fma2(a0A, vA[m], M0); fma2(a1A, vA[m], M1);
            fma2(a0B, vB[m], M0); fma2(a1B, vB[m], M1);
        }
        ull rA = mul2(pack2(xA.x, xA.x), a0A);
        fma2(rA, pack2(xA.y, xA.y), a1A);
        unpack2(rA, vA0, vA1);
        ull rB = mul2(pack2(xB.x, xB.x), a0B);
        fma2(rB, pack2(xB.y, xB.y), a1B);
        unpack2(rB, vB0, vB1);
    }

    // ---- publish chain results, fused combine ---------------------------------
    float* sL = sLR;
    float* sR = sLR + 128;
    {
        float* d = (isLeft ? sL : sR);
        d[sm0 * 16 + q] = vA0; d[sm0 * 16 + q + 8] = vA1;
        d[sm1 * 16 + q] = vB0; d[sm1 * 16 + q + 8] = vB1;
    }
    __syncthreads();

    float* sT = (float*)ring;               // reuse ring for T (NBL*1KB <= ring)
    int tElems = 256 * NBL;
    for (int i = tid; i < tElems; i += 64) sT[i] = __ldg(T + i);
    __syncthreads();

    int total = 8 * NBL;
    for (int i = tid; i < total; i += 64) {
        int b = i / NBL, l = i - b * NBL;
        float acc = 0.f;
#pragma unroll
        for (int m = 0; m < 16; ++m) {
            float t2 = 0.f;
#pragma unroll
            for (int k = 0; k < 16; ++k)
                t2 = fmaf(sT[(m * 16 + k) * NBL + l], sR[b * 16 + k], t2);
            acc = fmaf(sL[b * 16 + m], t2, acc);
        }
        out[(blockIdx.x * 8 + b) * NBL + l] = acc;
    }
}

// ---------------------------------------------------------------------------
extern "C" void kernel_launch(void* const* d_in, const int* in_sizes, int n_in,
                              void* d_out, int out_size) {
    const float* inputs  = (const float*)d_in[0];
    const float* A_left  = (const float*)d_in[1];
    const float* A_mid   = (const float*)d_in[2];
    const float* A_right = (const float*)d_in[3];
    const float* T_out   = (const float*)d_in[4];
    const int*   pos     = (const int*)d_in[5];

    int Lm2 = in_sizes[2] / 512;          // L-2 = 194
    int L   = Lm2 + 2;                    // 196
    int B   = in_sizes[0] / (2 * L);      // 2048
    int NBL = in_sizes[4] / 256;          // 10

    int PL = Lm2 >> 1;                    // 97
    int QMAX = PL >> 1;                   // 48
    prep_kernel<<<2 * PL, 256>>>(A_mid, Lm2);
    prep2_kernel<<<2 * QMAX, 256>>>(Lm2);

    int nblocks = B / 8;                  // 256 blocks, 512 warps
    size_t smemB = (size_t)RING_B + SV_B + SLR_B;   // ~101.5 KB

    cudaFuncSetAttribute(chain_kernel,
                         cudaFuncAttributeMaxDynamicSharedMemorySize,
                         (int)smemB);
    chain_kernel<<<nblocks, 64, smemB>>>(inputs, A_left, A_right,
                                         T_out, pos, (float*)d_out,
                                         B, L, NBL);
}